// round 2
// baseline (speedup 1.0000x reference)
#include <cuda_runtime.h>
#include <math.h>

// Problem constants
#define B_ 4
#define T_ 2048
#define E_ 1024
#define NH_ 16
#define DH_ 64
#define NE_ 2048
#define HID_ 16
#define M_ (B_ * T_)   // 8192 tokens

// ---------------- device scratch (no runtime allocation allowed) ----------------
__device__ float g_h[M_ * E_];          // LN output (reused for LN1 and LN2)
__device__ float g_qkv[M_ * 3 * E_];    // QKV
__device__ float g_attn[M_ * E_];       // attention output (pre-proj)
__device__ float g_x1[M_ * E_];         // x + attention branch
__device__ float g_logits[M_ * NE_];    // gate logits
__device__ int   g_idx[M_];             // argmax expert ids

// ---------------- LayerNorm: one block per token row ----------------
__global__ void ln_kernel(const float* __restrict__ x,
                          const float* __restrict__ g,
                          const float* __restrict__ b,
                          float* __restrict__ out) {
    int row = blockIdx.x;
    const float* xr = x + (size_t)row * E_;
    float s = 0.f, s2 = 0.f;
    for (int i = threadIdx.x; i < E_; i += 256) {
        float v = xr[i];
        s += v; s2 += v * v;
    }
    __shared__ float sh[20];
    #pragma unroll
    for (int o = 16; o > 0; o >>= 1) {
        s  += __shfl_down_sync(0xffffffffu, s,  o);
        s2 += __shfl_down_sync(0xffffffffu, s2, o);
    }
    int wid = threadIdx.x >> 5, lane = threadIdx.x & 31;
    if (lane == 0) { sh[wid] = s; sh[8 + wid] = s2; }
    __syncthreads();
    if (threadIdx.x == 0) {
        float ts = 0.f, ts2 = 0.f;
        #pragma unroll
        for (int w = 0; w < 8; w++) { ts += sh[w]; ts2 += sh[8 + w]; }
        float mu = ts * (1.0f / E_);
        float var = ts2 * (1.0f / E_) - mu * mu;
        sh[16] = mu;
        sh[17] = rsqrtf(var + 1e-5f);
    }
    __syncthreads();
    float mu = sh[16], rs = sh[17];
    float* orow = out + (size_t)row * E_;
    for (int i = threadIdx.x; i < E_; i += 256)
        orow[i] = (xr[i] - mu) * rs * g[i] + b[i];
}

// ---------------- SGEMM 128x128x8, 256 threads, 8x8 microtile ----------------
// C[M,N] = A[M,K] @ B[K,N] + bias[N] (+ res[M,N] if res != nullptr)
// Requires M%128==0, N%128==0, K%8==0 (true for all our shapes).
__global__ __launch_bounds__(256, 2)
void sgemm128(const float* __restrict__ A, const float* __restrict__ Bm,
              const float* __restrict__ bias, const float* __restrict__ res,
              float* __restrict__ C, int M, int N, int K) {
    __shared__ float As[8][128];
    __shared__ float Bs[8][128];
    int tid = threadIdx.x;
    int bx = blockIdx.x, by = blockIdx.y;

    const float* Ab = A + (size_t)by * 128 * K;
    const float* Bb = Bm + (size_t)bx * 128;

    int arow = tid >> 1, acol = (tid & 1) * 4;   // A tile: 128 rows x 8 k
    int brow = tid >> 5, bcol = (tid & 31) * 4;  // B tile: 8 k x 128 cols
    int tx = tid & 15, ty = tid >> 4;            // 16x16 thread grid

    float acc[8][8];
    #pragma unroll
    for (int i = 0; i < 8; i++)
        #pragma unroll
        for (int j = 0; j < 8; j++) acc[i][j] = 0.f;

    for (int k0 = 0; k0 < K; k0 += 8) {
        float4 a4 = *(const float4*)(Ab + (size_t)arow * K + k0 + acol);
        As[acol + 0][arow] = a4.x;
        As[acol + 1][arow] = a4.y;
        As[acol + 2][arow] = a4.z;
        As[acol + 3][arow] = a4.w;
        *(float4*)(&Bs[brow][bcol]) =
            *(const float4*)(Bb + (size_t)(k0 + brow) * N + bcol);
        __syncthreads();
        #pragma unroll
        for (int kk = 0; kk < 8; kk++) {
            float ar[8], br[8];
            *(float4*)(ar)     = *(const float4*)(&As[kk][ty * 8]);
            *(float4*)(ar + 4) = *(const float4*)(&As[kk][ty * 8 + 4]);
            *(float4*)(br)     = *(const float4*)(&Bs[kk][tx * 8]);
            *(float4*)(br + 4) = *(const float4*)(&Bs[kk][tx * 8 + 4]);
            #pragma unroll
            for (int i = 0; i < 8; i++)
                #pragma unroll
                for (int j = 0; j < 8; j++)
                    acc[i][j] = fmaf(ar[i], br[j], acc[i][j]);
        }
        __syncthreads();
    }

    int row0 = by * 128 + ty * 8;
    int col0 = bx * 128 + tx * 8;
    #pragma unroll
    for (int i = 0; i < 8; i++) {
        size_t off = (size_t)(row0 + i) * N + col0;
        #pragma unroll
        for (int j = 0; j < 8; j++) {
            float v = acc[i][j] + bias[col0 + j];
            if (res) v += res[off + j];
            C[off + j] = v;
        }
    }
}

// ---------------- Flash attention, fp32, 64x64 tiles ----------------
// grid: (T/64, B*NH), 128 threads. Dynamic smem: 4*64*65 floats + 3*64 floats.
#define ATTN_SMEM ((4 * 64 * 65 + 3 * 64) * 4)
__global__ void attn_kernel(const float* __restrict__ qkv,
                            float* __restrict__ out) {
    extern __shared__ float sm[];
    float* Qs  = sm;                 // [64][65]
    float* Ks  = Qs + 64 * 65;
    float* Vs  = Ks + 64 * 65;
    float* Ss  = Vs + 64 * 65;
    float* m_s = Ss + 64 * 65;       // [64]
    float* l_s = m_s + 64;
    float* a_s = l_s + 64;

    int tid = threadIdx.x;           // 128 threads
    int bh = blockIdx.y;
    int b = bh / NH_, h = bh % NH_;
    int qt = blockIdx.x;
    int q0 = qt * 64;
    int ty = tid >> 3, tx = tid & 7; // 16 x 8 -> 4q x 8col microtile

    // Load Q tile (pre-scaled by 1/sqrt(DH))
    for (int i = tid; i < 64 * 64; i += 128) {
        int r = i >> 6, d = i & 63;
        Qs[r * 65 + d] =
            qkv[((size_t)(b * T_ + q0 + r)) * 3072 + h * 64 + d] * 0.125f;
    }
    if (tid < 64) { m_s[tid] = -INFINITY; l_s[tid] = 0.f; }

    float O[4][8];
    #pragma unroll
    for (int i = 0; i < 4; i++)
        #pragma unroll
        for (int j = 0; j < 8; j++) O[i][j] = 0.f;
    __syncthreads();

    for (int kt = 0; kt <= qt; kt++) {
        int k0 = kt * 64;
        for (int i = tid; i < 64 * 64; i += 128) {
            int r = i >> 6, d = i & 63;
            size_t base = ((size_t)(b * T_ + k0 + r)) * 3072 + h * 64 + d;
            Ks[r * 65 + d] = qkv[base + 1024];
            Vs[r * 65 + d] = qkv[base + 2048];
        }
        __syncthreads();

        // S = Q @ K^T  (4x8 per thread)
        float acc[4][8];
        #pragma unroll
        for (int i = 0; i < 4; i++)
            #pragma unroll
            for (int j = 0; j < 8; j++) acc[i][j] = 0.f;
        for (int d = 0; d < 64; d++) {
            float ar[4], br[8];
            #pragma unroll
            for (int i = 0; i < 4; i++) ar[i] = Qs[(ty * 4 + i) * 65 + d];
            #pragma unroll
            for (int j = 0; j < 8; j++) br[j] = Ks[(tx * 8 + j) * 65 + d];
            #pragma unroll
            for (int i = 0; i < 4; i++)
                #pragma unroll
                for (int j = 0; j < 8; j++)
                    acc[i][j] = fmaf(ar[i], br[j], acc[i][j]);
        }
        bool diag = (kt == qt);
        #pragma unroll
        for (int i = 0; i < 4; i++) {
            int qi = ty * 4 + i;
            #pragma unroll
            for (int j = 0; j < 8; j++) {
                int kj = tx * 8 + j;
                float v = acc[i][j];
                if (diag && kj > qi) v = -INFINITY;
                Ss[qi * 65 + kj] = v;
            }
        }
        __syncthreads();

        // Online softmax row update (one thread per row)
        if (tid < 64) {
            float* srow = Ss + tid * 65;
            float mt = -INFINITY;
            #pragma unroll 8
            for (int j = 0; j < 64; j++) mt = fmaxf(mt, srow[j]);
            float mo = m_s[tid];
            float mn = fmaxf(mo, mt);
            float alpha = __expf(mo - mn);
            float sum = 0.f;
            #pragma unroll 8
            for (int j = 0; j < 64; j++) {
                float p = __expf(srow[j] - mn);
                srow[j] = p;
                sum += p;
            }
            m_s[tid] = mn;
            l_s[tid] = l_s[tid] * alpha + sum;
            a_s[tid] = alpha;
        }
        __syncthreads();

        // O = O*alpha + P @ V
        float al[4];
        #pragma unroll
        for (int i = 0; i < 4; i++) al[i] = a_s[ty * 4 + i];
        #pragma unroll
        for (int i = 0; i < 4; i++)
            #pragma unroll
            for (int j = 0; j < 8; j++) O[i][j] *= al[i];
        for (int k = 0; k < 64; k++) {
            float pr[4], vr[8];
            #pragma unroll
            for (int i = 0; i < 4; i++) pr[i] = Ss[(ty * 4 + i) * 65 + k];
            #pragma unroll
            for (int j = 0; j < 8; j++) vr[j] = Vs[k * 65 + tx * 8 + j];
            #pragma unroll
            for (int i = 0; i < 4; i++)
                #pragma unroll
                for (int j = 0; j < 8; j++)
                    O[i][j] = fmaf(pr[i], vr[j], O[i][j]);
        }
        __syncthreads();
    }

    #pragma unroll
    for (int i = 0; i < 4; i++) {
        int q = q0 + ty * 4 + i;
        float inv = 1.0f / l_s[ty * 4 + i];
        #pragma unroll
        for (int j = 0; j < 8; j++)
            out[((size_t)(b * T_ + q)) * E_ + h * 64 + tx * 8 + j] =
                O[i][j] * inv;
    }
}

// ---------------- argmax over NE logits, one block per token ----------------
__global__ void argmax_kernel(const float* __restrict__ logits,
                              int* __restrict__ idx) {
    int row = blockIdx.x;
    const float* lr = logits + (size_t)row * NE_;
    float best = -INFINITY;
    int bi = 0;
    for (int j = threadIdx.x; j < NE_; j += 256) {
        float v = lr[j];
        if (v > best) { best = v; bi = j; }
    }
    __shared__ float sv[256];
    __shared__ int si[256];
    sv[threadIdx.x] = best; si[threadIdx.x] = bi;
    __syncthreads();
    for (int s = 128; s > 0; s >>= 1) {
        if (threadIdx.x < s) {
            float v2 = sv[threadIdx.x + s];
            int i2 = si[threadIdx.x + s];
            if (v2 > sv[threadIdx.x] ||
                (v2 == sv[threadIdx.x] && i2 < si[threadIdx.x])) {
                sv[threadIdx.x] = v2; si[threadIdx.x] = i2;
            }
        }
        __syncthreads();
    }
    if (threadIdx.x == 0) idx[row] = si[0];
}

// ---------------- MoE expert apply + final residual, one block per token ----
__global__ void moe_kernel(const float* __restrict__ h2,
                           const int* __restrict__ idx,
                           const float* __restrict__ w1,
                           const float* __restrict__ b1,
                           const float* __restrict__ w2,
                           const float* __restrict__ b2,
                           const float* __restrict__ x1,
                           float* __restrict__ out) {
    int row = blockIdx.x;
    int e = idx[row];
    const float* xr = h2 + (size_t)row * E_;
    const float* W1 = w1 + (size_t)e * E_ * HID_;

    float acc[HID_];
    #pragma unroll
    for (int j = 0; j < HID_; j++) acc[j] = 0.f;

    for (int i = threadIdx.x; i < E_; i += 256) {
        float xv = xr[i];
        const float4* wr = (const float4*)(W1 + (size_t)i * HID_);
        float4 a = wr[0], b4 = wr[1], c = wr[2], d = wr[3];
        acc[0]  = fmaf(xv, a.x,  acc[0]);  acc[1]  = fmaf(xv, a.y,  acc[1]);
        acc[2]  = fmaf(xv, a.z,  acc[2]);  acc[3]  = fmaf(xv, a.w,  acc[3]);
        acc[4]  = fmaf(xv, b4.x, acc[4]);  acc[5]  = fmaf(xv, b4.y, acc[5]);
        acc[6]  = fmaf(xv, b4.z, acc[6]);  acc[7]  = fmaf(xv, b4.w, acc[7]);
        acc[8]  = fmaf(xv, c.x,  acc[8]);  acc[9]  = fmaf(xv, c.y,  acc[9]);
        acc[10] = fmaf(xv, c.z,  acc[10]); acc[11] = fmaf(xv, c.w,  acc[11]);
        acc[12] = fmaf(xv, d.x,  acc[12]); acc[13] = fmaf(xv, d.y,  acc[13]);
        acc[14] = fmaf(xv, d.z,  acc[14]); acc[15] = fmaf(xv, d.w,  acc[15]);
    }
    // warp reduce all 16, then cross-warp via smem
    #pragma unroll
    for (int o = 16; o > 0; o >>= 1)
        #pragma unroll
        for (int j = 0; j < HID_; j++)
            acc[j] += __shfl_down_sync(0xffffffffu, acc[j], o);

    __shared__ float ws[8][HID_];
    __shared__ float hm[HID_];
    int wid = threadIdx.x >> 5, lane = threadIdx.x & 31;
    if (lane == 0)
        #pragma unroll
        for (int j = 0; j < HID_; j++) ws[wid][j] = acc[j];
    __syncthreads();
    if (threadIdx.x < HID_) {
        float t = b1[(size_t)e * HID_ + threadIdx.x];
        #pragma unroll
        for (int w = 0; w < 8; w++) t += ws[w][threadIdx.x];
        // exact GELU
        hm[threadIdx.x] = 0.5f * t * (1.0f + erff(t * 0.70710678118654752f));
    }
    __syncthreads();

    const float* W2 = w2 + (size_t)e * HID_ * E_;
    const float* B2 = b2 + (size_t)e * E_;
    for (int c = threadIdx.x; c < E_; c += 256) {
        float y = B2[c];
        #pragma unroll
        for (int j = 0; j < HID_; j++)
            y = fmaf(hm[j], W2[(size_t)j * E_ + c], y);
        out[(size_t)row * E_ + c] = x1[(size_t)row * E_ + c] + y;
    }
}

// ---------------- host launcher ----------------
extern "C" void kernel_launch(void* const* d_in, const int* in_sizes, int n_in,
                              void* d_out, int out_size) {
    const float* x      = (const float*)d_in[0];
    const float* ln1_g  = (const float*)d_in[1];
    const float* ln1_b  = (const float*)d_in[2];
    const float* ln2_g  = (const float*)d_in[3];
    const float* ln2_b  = (const float*)d_in[4];
    const float* qkv_w  = (const float*)d_in[5];
    const float* qkv_b  = (const float*)d_in[6];
    const float* proj_w = (const float*)d_in[7];
    const float* proj_b = (const float*)d_in[8];
    const float* gate_w = (const float*)d_in[9];
    const float* gate_b = (const float*)d_in[10];
    const float* w1     = (const float*)d_in[11];
    const float* b1     = (const float*)d_in[12];
    const float* w2     = (const float*)d_in[13];
    const float* b2     = (const float*)d_in[14];
    float* out = (float*)d_out;

    float *h, *qkv, *attn, *x1, *logits;
    int* idx;
    cudaGetSymbolAddress((void**)&h, g_h);
    cudaGetSymbolAddress((void**)&qkv, g_qkv);
    cudaGetSymbolAddress((void**)&attn, g_attn);
    cudaGetSymbolAddress((void**)&x1, g_x1);
    cudaGetSymbolAddress((void**)&logits, g_logits);
    cudaGetSymbolAddress((void**)&idx, g_idx);

    cudaFuncSetAttribute(attn_kernel,
                         cudaFuncAttributeMaxDynamicSharedMemorySize, ATTN_SMEM);

    // 1) LN1
    ln_kernel<<<M_, 256>>>(x, ln1_g, ln1_b, h);
    // 2) QKV GEMM
    {
        dim3 g(3 * E_ / 128, M_ / 128);
        sgemm128<<<g, 256>>>(h, qkv_w, qkv_b, nullptr, qkv, M_, 3 * E_, E_);
    }
    // 3) causal flash attention
    {
        dim3 g(T_ / 64, B_ * NH_);
        attn_kernel<<<g, 128, ATTN_SMEM>>>(qkv, attn);
    }
    // 4) proj GEMM + residual(x) -> x1
    {
        dim3 g(E_ / 128, M_ / 128);
        sgemm128<<<g, 256>>>(attn, proj_w, proj_b, x, x1, M_, E_, E_);
    }
    // 5) LN2 (reuse h)
    ln_kernel<<<M_, 256>>>(x1, ln2_g, ln2_b, h);
    // 6) gate GEMM
    {
        dim3 g(NE_ / 128, M_ / 128);
        sgemm128<<<g, 256>>>(h, gate_w, gate_b, nullptr, logits, M_, NE_, E_);
    }
    // 7) argmax -> expert ids
    argmax_kernel<<<M_, 256>>>(logits, idx);
    // 8) MoE + final residual -> out
    moe_kernel<<<M_, 256>>>(h, idx, w1, b1, w2, b2, x1, out);
}

// round 6
// speedup vs baseline: 1.0540x; 1.0540x over previous
#include <cuda_runtime.h>
#include <math.h>

// Problem constants
#define B_ 4
#define T_ 2048
#define E_ 1024
#define NH_ 16
#define DH_ 64
#define NE_ 2048
#define HID_ 16
#define M_ (B_ * T_)   // 8192 tokens

// ---------------- device scratch (no runtime allocation allowed) ----------------
__device__ float g_h[M_ * E_];          // LN output (reused for LN1 and LN2)
__device__ float g_qkv[M_ * 3 * E_];    // QKV
__device__ float g_attn[M_ * E_];       // attention output (pre-proj)
__device__ float g_x1[M_ * E_];         // x + attention branch
__device__ float g_logits[M_ * NE_];    // gate logits
__device__ int   g_idx[M_];             // argmax expert ids

// ---------------- LayerNorm: one block per token row ----------------
__global__ void ln_kernel(const float* __restrict__ x,
                          const float* __restrict__ g,
                          const float* __restrict__ b,
                          float* __restrict__ out) {
    int row = blockIdx.x;
    const float* xr = x + (size_t)row * E_;
    float s = 0.f, s2 = 0.f;
    for (int i = threadIdx.x; i < E_; i += 256) {
        float v = xr[i];
        s += v; s2 += v * v;
    }
    __shared__ float sh[20];
    #pragma unroll
    for (int o = 16; o > 0; o >>= 1) {
        s  += __shfl_down_sync(0xffffffffu, s,  o);
        s2 += __shfl_down_sync(0xffffffffu, s2, o);
    }
    int wid = threadIdx.x >> 5, lane = threadIdx.x & 31;
    if (lane == 0) { sh[wid] = s; sh[8 + wid] = s2; }
    __syncthreads();
    if (threadIdx.x == 0) {
        float ts = 0.f, ts2 = 0.f;
        #pragma unroll
        for (int w = 0; w < 8; w++) { ts += sh[w]; ts2 += sh[8 + w]; }
        float mu = ts * (1.0f / E_);
        float var = ts2 * (1.0f / E_) - mu * mu;
        sh[16] = mu;
        sh[17] = rsqrtf(var + 1e-5f);
    }
    __syncthreads();
    float mu = sh[16], rs = sh[17];
    float* orow = out + (size_t)row * E_;
    for (int i = threadIdx.x; i < E_; i += 256)
        orow[i] = (xr[i] - mu) * rs * g[i] + b[i];
}

// ---------------- SGEMM 128x128x8, 256 threads, 8x8 microtile ----------------
__global__ __launch_bounds__(256, 2)
void sgemm128(const float* __restrict__ A, const float* __restrict__ Bm,
              const float* __restrict__ bias, const float* __restrict__ res,
              float* __restrict__ C, int M, int N, int K) {
    __shared__ float As[8][128];
    __shared__ float Bs[8][128];
    int tid = threadIdx.x;
    int bx = blockIdx.x, by = blockIdx.y;

    const float* Ab = A + (size_t)by * 128 * K;
    const float* Bb = Bm + (size_t)bx * 128;

    int arow = tid >> 1, acol = (tid & 1) * 4;
    int brow = tid >> 5, bcol = (tid & 31) * 4;
    int tx = tid & 15, ty = tid >> 4;

    float acc[8][8];
    #pragma unroll
    for (int i = 0; i < 8; i++)
        #pragma unroll
        for (int j = 0; j < 8; j++) acc[i][j] = 0.f;

    for (int k0 = 0; k0 < K; k0 += 8) {
        float4 a4 = *(const float4*)(Ab + (size_t)arow * K + k0 + acol);
        As[acol + 0][arow] = a4.x;
        As[acol + 1][arow] = a4.y;
        As[acol + 2][arow] = a4.z;
        As[acol + 3][arow] = a4.w;
        *(float4*)(&Bs[brow][bcol]) =
            *(const float4*)(Bb + (size_t)(k0 + brow) * N + bcol);
        __syncthreads();
        #pragma unroll
        for (int kk = 0; kk < 8; kk++) {
            float ar[8], br[8];
            *(float4*)(ar)     = *(const float4*)(&As[kk][ty * 8]);
            *(float4*)(ar + 4) = *(const float4*)(&As[kk][ty * 8 + 4]);
            *(float4*)(br)     = *(const float4*)(&Bs[kk][tx * 8]);
            *(float4*)(br + 4) = *(const float4*)(&Bs[kk][tx * 8 + 4]);
            #pragma unroll
            for (int i = 0; i < 8; i++)
                #pragma unroll
                for (int j = 0; j < 8; j++)
                    acc[i][j] = fmaf(ar[i], br[j], acc[i][j]);
        }
        __syncthreads();
    }

    int row0 = by * 128 + ty * 8;
    int col0 = bx * 128 + tx * 8;
    #pragma unroll
    for (int i = 0; i < 8; i++) {
        size_t off = (size_t)(row0 + i) * N + col0;
        #pragma unroll
        for (int j = 0; j < 8; j++) {
            float v = acc[i][j] + bias[col0 + j];
            if (res) v += res[off + j];
            C[off + j] = v;
        }
    }
}

// ---------------- Flash attention v2: 128q x 64k tiles, 256 threads ----------
// Layouts in dynamic smem (floats):
//   Qt[64][132]  : Q transposed (d-major, q contiguous), pre-scaled
//   Kt[64][68]   : K transposed (d-major, k contiguous)
//   Vs[64][68]   : V row-major  (k-major, d contiguous)
//   Ps[128][68]  : scores / probabilities
//   m_s[128], l_s[128], a_s[128]
#define QT_ST 132
#define KT_ST 68
#define ATTN_SMEM ((64 * QT_ST + 64 * KT_ST + 64 * KT_ST + 128 * KT_ST + 3 * 128) * 4)

__global__ __launch_bounds__(256, 1)
void attn_kernel(const float* __restrict__ qkv, float* __restrict__ out) {
    extern __shared__ float sm[];
    float* Qt  = sm;                       // 64*132
    float* Kt  = Qt + 64 * QT_ST;          // 64*68
    float* Vs  = Kt + 64 * KT_ST;          // 64*68
    float* Ps  = Vs + 64 * KT_ST;          // 128*68
    float* m_s = Ps + 128 * KT_ST;         // 128
    float* l_s = m_s + 128;
    float* a_s = l_s + 128;

    int tid = threadIdx.x;                 // 256 threads
    int bh = blockIdx.y;
    int b = bh / NH_, h = bh % NH_;
    int qt = blockIdx.x;
    int q0 = qt * 128;
    int ty = tid >> 4, tx = tid & 15;      // 16 x 16; microtile 8q x 4k

    // Load Q tile transposed, pre-scaled by 1/sqrt(DH)=0.125
    for (int i = tid; i < 128 * 64; i += 256) {
        int q = i >> 6, d = i & 63;
        Qt[d * QT_ST + q] =
            qkv[((size_t)(b * T_ + q0 + q)) * 3072 + h * 64 + d] * 0.125f;
    }
    if (tid < 128) { m_s[tid] = -INFINITY; l_s[tid] = 0.f; }

    float O[8][4];
    #pragma unroll
    for (int i = 0; i < 8; i++)
        #pragma unroll
        for (int j = 0; j < 4; j++) O[i][j] = 0.f;
    __syncthreads();

    int kt_max = 2 * qt + 1;   // k-tiles 0 .. kt_max (inclusive)
    for (int kt = 0; kt <= kt_max; kt++) {
        int k0 = kt * 64;
        // Load K (transposed) and V (row-major)
        for (int i = tid; i < 64 * 64; i += 256) {
            int k = i >> 6, d = i & 63;
            size_t base = ((size_t)(b * T_ + k0 + k)) * 3072 + h * 64 + d;
            Kt[d * KT_ST + k] = qkv[base + 1024];
            Vs[k * KT_ST + d] = qkv[base + 2048];
        }
        __syncthreads();

        // S = Q @ K^T : acc[8][4]
        float acc[8][4];
        #pragma unroll
        for (int i = 0; i < 8; i++)
            #pragma unroll
            for (int j = 0; j < 4; j++) acc[i][j] = 0.f;
        #pragma unroll 4
        for (int d = 0; d < 64; d++) {
            float ar[8], br[4];
            *(float4*)(ar)     = *(const float4*)(&Qt[d * QT_ST + ty * 8]);
            *(float4*)(ar + 4) = *(const float4*)(&Qt[d * QT_ST + ty * 8 + 4]);
            *(float4*)(br)     = *(const float4*)(&Kt[d * KT_ST + tx * 4]);
            #pragma unroll
            for (int i = 0; i < 8; i++)
                #pragma unroll
                for (int j = 0; j < 4; j++)
                    acc[i][j] = fmaf(ar[i], br[j], acc[i][j]);
        }

        bool need_mask = (k0 + 63 > q0);   // only last two k-tiles
        #pragma unroll
        for (int i = 0; i < 8; i++) {
            int qi = q0 + ty * 8 + i;
            #pragma unroll
            for (int j = 0; j < 4; j++) {
                int kj = k0 + tx * 4 + j;
                float v = acc[i][j];
                if (need_mask && kj > qi) v = -INFINITY;
                Ps[(ty * 8 + i) * KT_ST + tx * 4 + j] = v;
            }
        }
        __syncthreads();

        // Online softmax: 2 threads per row (32 cols each)
        {
            int r = tid >> 1, half = tid & 1;
            float* pr = Ps + r * KT_ST + half * 32;
            float mt = -INFINITY;
            #pragma unroll 8
            for (int j = 0; j < 32; j++) mt = fmaxf(mt, pr[j]);
            mt = fmaxf(mt, __shfl_xor_sync(0xffffffffu, mt, 1));
            float mo = m_s[r];
            float mn = fmaxf(mo, mt);
            float sum = 0.f;
            #pragma unroll 8
            for (int j = 0; j < 32; j++) {
                float p = __expf(pr[j] - mn);
                pr[j] = p;
                sum += p;
            }
            sum += __shfl_xor_sync(0xffffffffu, sum, 1);
            if (half == 0) {
                float alpha = __expf(mo - mn);
                m_s[r] = mn;
                l_s[r] = l_s[r] * alpha + sum;
                a_s[r] = alpha;
            }
        }
        __syncthreads();

        // O = O*alpha + P @ V
        float al[8];
        #pragma unroll
        for (int i = 0; i < 8; i++) al[i] = a_s[ty * 8 + i];
        #pragma unroll
        for (int i = 0; i < 8; i++)
            #pragma unroll
            for (int j = 0; j < 4; j++) O[i][j] *= al[i];
        #pragma unroll 4
        for (int k = 0; k < 64; k++) {
            float pr[8], vr[4];
            #pragma unroll
            for (int i = 0; i < 8; i++) pr[i] = Ps[(ty * 8 + i) * KT_ST + k];
            *(float4*)(vr) = *(const float4*)(&Vs[k * KT_ST + tx * 4]);
            #pragma unroll
            for (int i = 0; i < 8; i++)
                #pragma unroll
                for (int j = 0; j < 4; j++)
                    O[i][j] = fmaf(pr[i], vr[j], O[i][j]);
        }
        __syncthreads();
    }

    #pragma unroll
    for (int i = 0; i < 8; i++) {
        int q = q0 + ty * 8 + i;
        float inv = 1.0f / l_s[ty * 8 + i];
        #pragma unroll
        for (int j = 0; j < 4; j++)
            out[((size_t)(b * T_ + q)) * E_ + h * 64 + tx * 4 + j] =
                O[i][j] * inv;
    }
}

// ---------------- argmax over NE logits, one block per token ----------------
__global__ void argmax_kernel(const float* __restrict__ logits,
                              int* __restrict__ idx) {
    int row = blockIdx.x;
    const float* lr = logits + (size_t)row * NE_;
    float best = -INFINITY;
    int bi = 0;
    for (int j = threadIdx.x; j < NE_; j += 256) {
        float v = lr[j];
        if (v > best) { best = v; bi = j; }
    }
    __shared__ float sv[256];
    __shared__ int si[256];
    sv[threadIdx.x] = best; si[threadIdx.x] = bi;
    __syncthreads();
    for (int s = 128; s > 0; s >>= 1) {
        if (threadIdx.x < s) {
            float v2 = sv[threadIdx.x + s];
            int i2 = si[threadIdx.x + s];
            if (v2 > sv[threadIdx.x] ||
                (v2 == sv[threadIdx.x] && i2 < si[threadIdx.x])) {
                sv[threadIdx.x] = v2; si[threadIdx.x] = i2;
            }
        }
        __syncthreads();
    }
    if (threadIdx.x == 0) idx[row] = si[0];
}

// ---------------- MoE expert apply + final residual, one block per token ----
__global__ void moe_kernel(const float* __restrict__ h2,
                           const int* __restrict__ idx,
                           const float* __restrict__ w1,
                           const float* __restrict__ b1,
                           const float* __restrict__ w2,
                           const float* __restrict__ b2,
                           const float* __restrict__ x1,
                           float* __restrict__ out) {
    int row = blockIdx.x;
    int e = idx[row];
    const float* xr = h2 + (size_t)row * E_;
    const float* W1 = w1 + (size_t)e * E_ * HID_;

    float acc[HID_];
    #pragma unroll
    for (int j = 0; j < HID_; j++) acc[j] = 0.f;

    for (int i = threadIdx.x; i < E_; i += 256) {
        float xv = xr[i];
        const float4* wr = (const float4*)(W1 + (size_t)i * HID_);
        float4 a = wr[0], b4 = wr[1], c = wr[2], d = wr[3];
        acc[0]  = fmaf(xv, a.x,  acc[0]);  acc[1]  = fmaf(xv, a.y,  acc[1]);
        acc[2]  = fmaf(xv, a.z,  acc[2]);  acc[3]  = fmaf(xv, a.w,  acc[3]);
        acc[4]  = fmaf(xv, b4.x, acc[4]);  acc[5]  = fmaf(xv, b4.y, acc[5]);
        acc[6]  = fmaf(xv, b4.z, acc[6]);  acc[7]  = fmaf(xv, b4.w, acc[7]);
        acc[8]  = fmaf(xv, c.x,  acc[8]);  acc[9]  = fmaf(xv, c.y,  acc[9]);
        acc[10] = fmaf(xv, c.z,  acc[10]); acc[11] = fmaf(xv, c.w,  acc[11]);
        acc[12] = fmaf(xv, d.x,  acc[12]); acc[13] = fmaf(xv, d.y,  acc[13]);
        acc[14] = fmaf(xv, d.z,  acc[14]); acc[15] = fmaf(xv, d.w,  acc[15]);
    }
    #pragma unroll
    for (int o = 16; o > 0; o >>= 1)
        #pragma unroll
        for (int j = 0; j < HID_; j++)
            acc[j] += __shfl_down_sync(0xffffffffu, acc[j], o);

    __shared__ float ws[8][HID_];
    __shared__ float hm[HID_];
    int wid = threadIdx.x >> 5, lane = threadIdx.x & 31;
    if (lane == 0)
        #pragma unroll
        for (int j = 0; j < HID_; j++) ws[wid][j] = acc[j];
    __syncthreads();
    if (threadIdx.x < HID_) {
        float t = b1[(size_t)e * HID_ + threadIdx.x];
        #pragma unroll
        for (int w = 0; w < 8; w++) t += ws[w][threadIdx.x];
        hm[threadIdx.x] = 0.5f * t * (1.0f + erff(t * 0.70710678118654752f));
    }
    __syncthreads();

    const float* W2 = w2 + (size_t)e * HID_ * E_;
    const float* B2 = b2 + (size_t)e * E_;
    for (int c = threadIdx.x; c < E_; c += 256) {
        float y = B2[c];
        #pragma unroll
        for (int j = 0; j < HID_; j++)
            y = fmaf(hm[j], W2[(size_t)j * E_ + c], y);
        out[(size_t)row * E_ + c] = x1[(size_t)row * E_ + c] + y;
    }
}

// ---------------- host launcher ----------------
extern "C" void kernel_launch(void* const* d_in, const int* in_sizes, int n_in,
                              void* d_out, int out_size) {
    const float* x      = (const float*)d_in[0];
    const float* ln1_g  = (const float*)d_in[1];
    const float* ln1_b  = (const float*)d_in[2];
    const float* ln2_g  = (const float*)d_in[3];
    const float* ln2_b  = (const float*)d_in[4];
    const float* qkv_w  = (const float*)d_in[5];
    const float* qkv_b  = (const float*)d_in[6];
    const float* proj_w = (const float*)d_in[7];
    const float* proj_b = (const float*)d_in[8];
    const float* gate_w = (const float*)d_in[9];
    const float* gate_b = (const float*)d_in[10];
    const float* w1     = (const float*)d_in[11];
    const float* b1     = (const float*)d_in[12];
    const float* w2     = (const float*)d_in[13];
    const float* b2     = (const float*)d_in[14];
    float* out = (float*)d_out;

    float *h, *qkv, *attn, *x1, *logits;
    int* idx;
    cudaGetSymbolAddress((void**)&h, g_h);
    cudaGetSymbolAddress((void**)&qkv, g_qkv);
    cudaGetSymbolAddress((void**)&attn, g_attn);
    cudaGetSymbolAddress((void**)&x1, g_x1);
    cudaGetSymbolAddress((void**)&logits, g_logits);
    cudaGetSymbolAddress((void**)&idx, g_idx);

    cudaFuncSetAttribute(attn_kernel,
                         cudaFuncAttributeMaxDynamicSharedMemorySize, ATTN_SMEM);

    // 1) LN1
    ln_kernel<<<M_, 256>>>(x, ln1_g, ln1_b, h);
    // 2) QKV GEMM
    {
        dim3 g(3 * E_ / 128, M_ / 128);
        sgemm128<<<g, 256>>>(h, qkv_w, qkv_b, nullptr, qkv, M_, 3 * E_, E_);
    }
    // 3) causal flash attention (128q x 64k tiles)
    {
        dim3 g(T_ / 128, B_ * NH_);
        attn_kernel<<<g, 256, ATTN_SMEM>>>(qkv, attn);
    }
    // 4) proj GEMM + residual(x) -> x1
    {
        dim3 g(E_ / 128, M_ / 128);
        sgemm128<<<g, 256>>>(attn, proj_w, proj_b, x, x1, M_, E_, E_);
    }
    // 5) LN2 (reuse h)
    ln_kernel<<<M_, 256>>>(x1, ln2_g, ln2_b, h);
    // 6) gate GEMM
    {
        dim3 g(NE_ / 128, M_ / 128);
        sgemm128<<<g, 256>>>(h, gate_w, gate_b, nullptr, logits, M_, NE_, E_);
    }
    // 7) argmax -> expert ids
    argmax_kernel<<<M_, 256>>>(logits, idx);
    // 8) MoE + final residual -> out
    moe_kernel<<<M_, 256>>>(h, idx, w1, b1, w2, b2, x1, out);
}